// round 9
// baseline (speedup 1.0000x reference)
#include <cuda_runtime.h>
#include <cstddef>
#include <cstdint>

#define NPTS 1000000
#define KSZ 9
#define EPSBN 1e-5f
#define NF4 (NPTS * 16 / 4)
#define CONVGRID 15625            // 64 points per block, exact: 15625*64 = 1M
#define MIDB 64
#define RPB ((CONVGRID + MIDB - 1) / MIDB)   // 245
#define SGRID 1184
#define SSTRIDE (SGRID * 256)

typedef unsigned long long ull;

// ---------------- scratch (device globals: no allocation) ----------------
__device__ float g_h[(size_t)NPTS * 16];           // conv1 raw output, 64 MB
__device__ float4 g_part4[CONVGRID * 8];           // per-block stats partials
__device__ float g_mid[MIDB * 32];
__device__ __align__(16) float g_st1[32];          // BN1 scale[16], shift[16]
__device__ __align__(16) float g_st2[32];          // BN2 scale[16], shift[16]

// ---------------- f32x2 packed helpers ----------------
__device__ __forceinline__ ull pack2(float lo, float hi) {
    ull r; asm("mov.b64 %0, {%1, %2};" : "=l"(r) : "f"(lo), "f"(hi)); return r;
}
__device__ __forceinline__ void unpack2(ull v, float& lo, float& hi) {
    asm("mov.b64 {%0, %1}, %2;" : "=f"(lo), "=f"(hi) : "l"(v));
}
__device__ __forceinline__ ull fma2(ull a, ull b, ull c) {
    ull d; asm("fma.rn.f32x2 %0, %1, %2, %3;" : "=l"(d) : "l"(a), "l"(b), "l"(c)); return d;
}

// =====================================================================
// Tree-conv, cp.async-staged gather.
//  Block = 128 threads, tile = 64 points (grid exact: 15625*64 = 1M).
//  Stage: cp.async.cg 16B per (u-chunk, j, point) -> sdat[u][j][p]
//         (p-contiguous 16B chunks => compute LDS is 128B/warp, 1 wf)
//  Compute: thread = (q = o-quarter, grp) handling points {grp, grp+32}.
//         Per (j,c): 1 broadcast LDS.128 of w[j][c][4q..4q+3] (64B/warp),
//         2 pack2 + 4 fma2. No shuffles; thread owns its 4 outputs.
//  Stats: per-block channel sums/sumsq reduced in smem (deterministic).
// =====================================================================
template <bool BIAS>
__global__ void __launch_bounds__(128) conv_kernel(
    const float* __restrict__ src, const int* __restrict__ ind,
    const float* __restrict__ w, const float* __restrict__ bias,
    float* __restrict__ dst)
{
    __shared__ __align__(16) float4 sdat[4 * KSZ * 64];   // [u][j][p]  36,864 B
    __shared__ __align__(16) float wsm[KSZ * 16 * 16];    // [j][c][o]   9,216 B
    const int tid = threadIdx.x;
    const int q = tid & 3;
    const int grp = tid >> 2;            // 0..31
    const int pbase = blockIdx.x * 64;

    // ---- stage weights: w[c][o][j] -> wsm[j][c][o] ----
    for (int i = tid; i < 16 * 16 * KSZ; i += 128) {
        int c = i / 144;
        int rem = i - c * 144;
        int o = rem / 9;
        int j = rem - o * 9;
        wsm[(j * 16 + c) * 16 + o] = w[i];
    }

    // ---- stage gathered rows via cp.async (deep queue, no reg pressure) ----
    const float4* sp = reinterpret_cast<const float4*>(src);
#pragma unroll
    for (int t = 0; t < 18; t++) {
        int i = tid + 128 * t;                 // 0..2303
        int u = i & 3;
        int jp = i >> 2;                       // 0..575
        int j = jp % KSZ;
        int p = jp / KSZ;                      // 0..63
        int row = __ldg(ind + (pbase + p) * KSZ + j);
        const float4* gsrc = sp + (size_t)row * 4 + u;
        uint32_t saddr = (uint32_t)__cvta_generic_to_shared(&sdat[(u * KSZ + j) * 64 + p]);
        asm volatile("cp.async.cg.shared.global [%0], [%1], 16;"
                     :: "r"(saddr), "l"(gsrc));
    }
    asm volatile("cp.async.commit_group;");
    asm volatile("cp.async.wait_group 0;" ::: "memory");
    __syncthreads();

    // ---- compute ----
    ull acc0x = 0, acc0y = 0, acc1x = 0, acc1y = 0;   // 2 points x (o pair0, pair1)

    for (int j = 0; j < KSZ; j++) {
        float4 A0[4], A1[4];
#pragma unroll
        for (int u = 0; u < 4; u++) {
            A0[u] = sdat[(u * KSZ + j) * 64 + grp];
            A1[u] = sdat[(u * KSZ + j) * 64 + grp + 32];
        }
        const float* wj = wsm + j * 256;
#pragma unroll
        for (int c = 0; c < 16; c++) {
            const float v0 = (&A0[c >> 2].x)[c & 3];
            const float v1 = (&A1[c >> 2].x)[c & 3];
            ulonglong2 ww = *reinterpret_cast<const ulonglong2*>(wj + c * 16 + q * 4);
            const ull v0p = pack2(v0, v0);
            const ull v1p = pack2(v1, v1);
            acc0x = fma2(v0p, ww.x, acc0x);
            acc0y = fma2(v0p, ww.y, acc0y);
            acc1x = fma2(v1p, ww.x, acc1x);
            acc1y = fma2(v1p, ww.y, acc1y);
        }
    }

    // ---- bias, store, per-thread stats ----
    float o0[2], o1[2], o2[2], o3[2];
    unpack2(acc0x, o0[0], o1[0]); unpack2(acc0y, o2[0], o3[0]);
    unpack2(acc1x, o0[1], o1[1]); unpack2(acc1y, o2[1], o3[1]);
    if (BIAS) {
        float4 b4 = reinterpret_cast<const float4*>(bias)[q];
#pragma unroll
        for (int k = 0; k < 2; k++) {
            o0[k] += b4.x; o1[k] += b4.y; o2[k] += b4.z; o3[k] += b4.w;
        }
    }
    float4 s4 = make_float4(0.f, 0.f, 0.f, 0.f);
    float4 q4 = make_float4(0.f, 0.f, 0.f, 0.f);
#pragma unroll
    for (int k = 0; k < 2; k++) {
        const int p = pbase + grp + 32 * k;
        reinterpret_cast<float4*>(dst)[(size_t)p * 4 + q] =
            make_float4(o0[k], o1[k], o2[k], o3[k]);
        s4.x += o0[k]; s4.y += o1[k]; s4.z += o2[k]; s4.w += o3[k];
        q4.x += o0[k] * o0[k]; q4.y += o1[k] * o1[k];
        q4.z += o2[k] * o2[k]; q4.w += o3[k] * o3[k];
    }

    // ---- per-block stats reduce (reuse wsm region; deterministic) ----
    __syncthreads();
    float4* s1 = reinterpret_cast<float4*>(wsm);       // 128 float4 = 2KB
    float4* s2 = s1 + 128;                             // 2KB
    s1[tid] = s4; s2[tid] = q4;
    __syncthreads();
#pragma unroll
    for (int off = 64; off >= 4; off >>= 1) {
        if (tid < off) {
            float4 a = s1[tid], b = s1[tid + off];
            a.x += b.x; a.y += b.y; a.z += b.z; a.w += b.w; s1[tid] = a;
            float4 c = s2[tid], d = s2[tid + off];
            c.x += d.x; c.y += d.y; c.z += d.z; c.w += d.w; s2[tid] = c;
        }
        __syncthreads();
    }
    if (tid < 4) {
        g_part4[blockIdx.x * 8 + tid] = s1[tid];       // sums, channels 4*tid..
        g_part4[blockIdx.x * 8 + 4 + tid] = s2[tid];   // squares
    }
}

// ---------------- BN1 + leaky applied in place on g_h ----------------
__global__ __launch_bounds__(256) void bnapply_kernel()
{
    const int tid = threadIdx.x;
    const int idx = blockIdx.x * 256 + tid;
    const int g = tid & 3;
    float4 sc = reinterpret_cast<const float4*>(g_st1)[g];
    float4 sh = reinterpret_cast<const float4*>(g_st1 + 16)[g];
    float4* hh = reinterpret_cast<float4*>(g_h);
    for (int i = idx; i < NF4; i += SSTRIDE) {
        float4 v = hh[i];
        v.x = fmaf(v.x, sc.x, sh.x); v.x = fmaxf(v.x, 0.2f * v.x);
        v.y = fmaf(v.y, sc.y, sh.y); v.y = fmaxf(v.y, 0.2f * v.y);
        v.z = fmaf(v.z, sc.z, sh.z); v.z = fmaxf(v.z, 0.2f * v.z);
        v.w = fmaf(v.w, sc.w, sh.w); v.w = fmaxf(v.w, 0.2f * v.w);
        hh[i] = v;
    }
}

// ---------------- mid-stage stats reduction: CONVGRID -> 64 partials ----------------
__global__ __launch_bounds__(256) void midstats_kernel()
{
    const float* part = reinterpret_cast<const float*>(g_part4);
    const int tid = threadIdx.x;
    const int v = tid & 31;
    const int lane = tid >> 5;
    const int r0 = blockIdx.x * RPB;
    const int rend = min(r0 + RPB, CONVGRID);
    float loc = 0.f;
    for (int r = r0 + lane; r < rend; r += 8) loc += part[r * 32 + v];
    __shared__ float sm[256];
    sm[tid] = loc;
    __syncthreads();
    if (tid < 32) {
        float t = 0.f;
#pragma unroll
        for (int k = 0; k < 8; k++) t += sm[tid + k * 32];
        g_mid[blockIdx.x * 32 + tid] = t;
    }
}

// ---------------- finalize: 64 partials -> BN scale/shift ----------------
template <int S>
__global__ void finalize_kernel(const float* __restrict__ gamma,
                                const float* __restrict__ beta)
{
    const int tid = threadIdx.x;   // 32 threads
    __shared__ float sm[32];
    float t = 0.f;
    for (int r = 0; r < MIDB; r++) t += g_mid[r * 32 + tid];
    sm[tid] = t;
    __syncthreads();
    if (tid < 16) {
        const float inv_n = 1.0f / (float)NPTS;
        float mean = sm[tid] * inv_n;
        float var = sm[16 + tid] * inv_n - mean * mean;
        float rstd = rsqrtf(var + EPSBN);
        float sc = gamma[tid] * rstd;
        float sh = beta[tid] - mean * sc;
        float* st = (S == 1) ? g_st1 : g_st2;
        st[tid] = sc;
        st[16 + tid] = sh;
    }
}

// ---------- epilogue: out = leaky(BN2(raw2) + data), in place on d_out ----------
__global__ __launch_bounds__(256) void bnres_kernel(
    const float* __restrict__ data, float* __restrict__ out)
{
    const int tid = threadIdx.x;
    const int idx = blockIdx.x * 256 + tid;
    const int g = tid & 3;
    float4 sc = reinterpret_cast<const float4*>(g_st2)[g];
    float4 sh = reinterpret_cast<const float4*>(g_st2 + 16)[g];
    const float4* dd = reinterpret_cast<const float4*>(data);
    float4* oo = reinterpret_cast<float4*>(out);
    for (int i = idx; i < NF4; i += SSTRIDE) {
        float4 r = oo[i];
        float4 d = dd[i];
        float4 y;
        y.x = fmaf(r.x, sc.x, sh.x) + d.x;
        y.y = fmaf(r.y, sc.y, sh.y) + d.y;
        y.z = fmaf(r.z, sc.z, sh.z) + d.z;
        y.w = fmaf(r.w, sc.w, sh.w) + d.w;
        y.x = fmaxf(y.x, 0.2f * y.x);
        y.y = fmaxf(y.y, 0.2f * y.y);
        y.z = fmaxf(y.z, 0.2f * y.z);
        y.w = fmaxf(y.w, 0.2f * y.w);
        oo[i] = y;
    }
}

extern "C" void kernel_launch(void* const* d_in, const int* in_sizes, int n_in,
                              void* d_out, int out_size)
{
    const float* data   = (const float*)d_in[0];
    const int*   ind    = (const int*)  d_in[1];
    const float* w1     = (const float*)d_in[2];
    const float* b1     = (const float*)d_in[3];
    const float* gamma1 = (const float*)d_in[4];
    const float* beta1  = (const float*)d_in[5];
    const float* w2     = (const float*)d_in[6];
    const float* gamma2 = (const float*)d_in[7];
    const float* beta2  = (const float*)d_in[8];
    float* out = (float*)d_out;

    float* gh;
    cudaGetSymbolAddress((void**)&gh, g_h);

    conv_kernel<true><<<CONVGRID, 128>>>(data, ind, w1, b1, gh);
    midstats_kernel<<<MIDB, 256>>>();
    finalize_kernel<1><<<1, 32>>>(gamma1, beta1);
    bnapply_kernel<<<SGRID, 256>>>();                      // BN1+leaky on g_h
    conv_kernel<false><<<CONVGRID, 128>>>(gh, ind, w2, nullptr, out);
    midstats_kernel<<<MIDB, 256>>>();
    finalize_kernel<2><<<1, 32>>>(gamma2, beta2);
    bnres_kernel<<<SGRID, 256>>>(data, out);
}